// round 1
// baseline (speedup 1.0000x reference)
#include <cuda_runtime.h>

#define Bc   4
#define Nn   1024
#define Ee   1024
#define Hh   16
#define DhD  64
#define BHn  64
#define Mtot 4096   // B*N

// Scratch for projected q/k/v in natural [B,N,E] layout (raw-view indexing used later).
__device__ float g_q[Mtot * Ee];
__device__ float g_k[Mtot * Ee];
__device__ float g_v[Mtot * Ee];
// Fallback weights buffer if the harness output only holds attn.
__device__ float g_w[(size_t)BHn * Nn * Nn];

// ---------------------------------------------------------------------------
// Projection GEMM: C = X @ W^T + b.  X[M,K], W[N,K], K-major both (NT GEMM).
// 128x128x8 tiles, 256 threads, 8x8 microtile.
// ---------------------------------------------------------------------------
__global__ __launch_bounds__(256) void proj_kernel(
    const float* __restrict__ Xq, const float* __restrict__ Xk, const float* __restrict__ Xv,
    const float* __restrict__ Wq, const float* __restrict__ Wk, const float* __restrict__ Wv,
    const float* __restrict__ bq, const float* __restrict__ bk, const float* __restrict__ bv)
{
    const float* X; const float* W; const float* bias; float* C;
    if (blockIdx.z == 0)      { X = Xq; W = Wq; bias = bq; C = g_q; }
    else if (blockIdx.z == 1) { X = Xk; W = Wk; bias = bk; C = g_k; }
    else                      { X = Xv; W = Wv; bias = bv; C = g_v; }

    __shared__ float As[8][128];
    __shared__ float Bs[8][128];

    const int tid = threadIdx.x;
    const int bm = blockIdx.y * 128;
    const int bn = blockIdx.x * 128;
    const int lr = tid >> 1;            // 0..127
    const int lc = (tid & 1) * 4;       // 0 or 4
    const int tm = (tid >> 4) * 8;      // 0..120
    const int tn = (tid & 15) * 8;      // 0..120

    const float* Xp = X + (size_t)(bm + lr) * 1024 + lc;
    const float* Wp = W + (size_t)(bn + lr) * 1024 + lc;

    float acc[8][8];
    #pragma unroll
    for (int i = 0; i < 8; i++)
        #pragma unroll
        for (int j = 0; j < 8; j++) acc[i][j] = 0.0f;

    for (int k0 = 0; k0 < 1024; k0 += 8) {
        float4 a = *reinterpret_cast<const float4*>(Xp + k0);
        float4 b = *reinterpret_cast<const float4*>(Wp + k0);
        __syncthreads();
        As[lc + 0][lr] = a.x; As[lc + 1][lr] = a.y; As[lc + 2][lr] = a.z; As[lc + 3][lr] = a.w;
        Bs[lc + 0][lr] = b.x; Bs[lc + 1][lr] = b.y; Bs[lc + 2][lr] = b.z; Bs[lc + 3][lr] = b.w;
        __syncthreads();
        #pragma unroll
        for (int k = 0; k < 8; k++) {
            float4 a0 = *reinterpret_cast<const float4*>(&As[k][tm]);
            float4 a1 = *reinterpret_cast<const float4*>(&As[k][tm + 4]);
            float4 b0 = *reinterpret_cast<const float4*>(&Bs[k][tn]);
            float4 b1 = *reinterpret_cast<const float4*>(&Bs[k][tn + 4]);
            float av[8] = {a0.x, a0.y, a0.z, a0.w, a1.x, a1.y, a1.z, a1.w};
            float bw[8] = {b0.x, b0.y, b0.z, b0.w, b1.x, b1.y, b1.z, b1.w};
            #pragma unroll
            for (int i = 0; i < 8; i++)
                #pragma unroll
                for (int j = 0; j < 8; j++)
                    acc[i][j] += av[i] * bw[j];
        }
    }

    float4 bb0 = *reinterpret_cast<const float4*>(bias + bn + tn);
    float4 bb1 = *reinterpret_cast<const float4*>(bias + bn + tn + 4);
    float bvv[8] = {bb0.x, bb0.y, bb0.z, bb0.w, bb1.x, bb1.y, bb1.z, bb1.w};
    #pragma unroll
    for (int i = 0; i < 8; i++) {
        float* Cp = C + (size_t)(bm + tm + i) * 1024 + bn + tn;
        float4 o0, o1;
        o0.x = acc[i][0] + bvv[0]; o0.y = acc[i][1] + bvv[1];
        o0.z = acc[i][2] + bvv[2]; o0.w = acc[i][3] + bvv[3];
        o1.x = acc[i][4] + bvv[4]; o1.y = acc[i][5] + bvv[5];
        o1.z = acc[i][6] + bvv[6]; o1.w = acc[i][7] + bvv[7];
        *reinterpret_cast<float4*>(Cp)     = o0;
        *reinterpret_cast<float4*>(Cp + 4) = o1;
    }
}

// ---------------------------------------------------------------------------
// Attention: one CTA per (bh, 32-row tile). Full 32x1024 score block in smem.
// ---------------------------------------------------------------------------
#define RT 32
#define CT 128
#define QS_STRIDE 36    // Qs[d][i], 64 x 36
#define KS_STRIDE 132   // Ks[d][c], 64 x 132
#define VS_STRIDE 68    // Vs[c][d], 128 x 68
#define SMEM_FLOATS (RT * 1024 + 64 * QS_STRIDE + CT * VS_STRIDE)

__global__ __launch_bounds__(256) void attn_kernel(
    const float* __restrict__ bias, float* __restrict__ out_attn, float* __restrict__ w_out)
{
    extern __shared__ float sm[];
    float* S  = sm;                       // [RT][1024]
    float* Qs = S + RT * 1024;            // [64][QS_STRIDE]
    float* KV = Qs + 64 * QS_STRIDE;      // union of Ks / Vs

    const int tid = threadIdx.x;
    const int bh  = blockIdx.y;           // 0..63
    const int r0  = blockIdx.x * RT;      // row tile base

    const float* qb = g_q + bh * 64;      // q_view[bh,r,d] = qb[r*4096 + d]
    const float* kb = g_k + bh * 64;
    const float* vb = g_v + bh * 64;
    const float* bsrc = bias + (size_t)(bh & 3) * Nn * Nn;
    float* wbase = (w_out != nullptr) ? w_out : g_w;
    float* wrow_base = wbase + (size_t)bh * Nn * Nn;

    // ---- load Q tile transposed: Qs[d][i] ----
    #pragma unroll
    for (int s = 0; s < 2; s++) {
        int idx = tid + 256 * s;          // 0..511
        int i  = idx & 31;
        int d0 = (idx >> 5) * 4;
        float4 v = *reinterpret_cast<const float4*>(qb + (size_t)(r0 + i) * 4096 + d0);
        Qs[(d0 + 0) * QS_STRIDE + i] = v.x;
        Qs[(d0 + 1) * QS_STRIDE + i] = v.y;
        Qs[(d0 + 2) * QS_STRIDE + i] = v.z;
        Qs[(d0 + 3) * QS_STRIDE + i] = v.w;
    }

    // ---- scores: S[i][c] = sum_d Q[i,d]*K[c,d] + bias ----
    const int si0 = (tid >> 5) * 4;       // 0..28
    const int sc0 = (tid & 31) * 4;       // 0..124

    for (int ct = 0; ct < 8; ct++) {
        __syncthreads();                  // prev compute done (and Q load on ct=0)
        // load K tile transposed: Ks[d][c], c fast per warp -> conflict-free stores
        #pragma unroll
        for (int s = 0; s < 8; s++) {
            int idx = tid + 256 * s;      // 0..2047
            int c  = idx & 127;
            int d0 = (idx >> 7) * 4;
            float4 v = *reinterpret_cast<const float4*>(kb + (size_t)(ct * CT + c) * 4096 + d0);
            KV[(d0 + 0) * KS_STRIDE + c] = v.x;
            KV[(d0 + 1) * KS_STRIDE + c] = v.y;
            KV[(d0 + 2) * KS_STRIDE + c] = v.z;
            KV[(d0 + 3) * KS_STRIDE + c] = v.w;
        }
        __syncthreads();

        float acc[4][4];
        #pragma unroll
        for (int i = 0; i < 4; i++)
            #pragma unroll
            for (int j = 0; j < 4; j++) acc[i][j] = 0.0f;

        #pragma unroll 4
        for (int d = 0; d < 64; d++) {
            float4 a = *reinterpret_cast<const float4*>(&Qs[d * QS_STRIDE + si0]);
            float4 b = *reinterpret_cast<const float4*>(&KV[d * KS_STRIDE + sc0]);
            float av[4] = {a.x, a.y, a.z, a.w};
            float bv[4] = {b.x, b.y, b.z, b.w};
            #pragma unroll
            for (int i = 0; i < 4; i++)
                #pragma unroll
                for (int j = 0; j < 4; j++)
                    acc[i][j] += av[i] * bv[j];
        }

        #pragma unroll
        for (int ii = 0; ii < 4; ii++) {
            float4 bv4 = *reinterpret_cast<const float4*>(
                bsrc + (size_t)(r0 + si0 + ii) * Nn + ct * CT + sc0);
            float4 o;
            o.x = acc[ii][0] + bv4.x; o.y = acc[ii][1] + bv4.y;
            o.z = acc[ii][2] + bv4.z; o.w = acc[ii][3] + bv4.w;
            *reinterpret_cast<float4*>(&S[(si0 + ii) * 1024 + ct * CT + sc0]) = o;
        }
    }
    __syncthreads();

    // ---- softmax per row (8 warps x 4 rows) + stream weights out ----
    {
        const int warp = tid >> 5, lane = tid & 31;
        #pragma unroll
        for (int rr = 0; rr < 4; rr++) {
            int i = warp * 4 + rr;
            float* row = &S[i * 1024];
            float m = -3.0e38f;
            #pragma unroll 8
            for (int c = lane; c < 1024; c += 32) m = fmaxf(m, row[c]);
            #pragma unroll
            for (int o = 16; o > 0; o >>= 1) m = fmaxf(m, __shfl_xor_sync(0xffffffffu, m, o));
            float ssum = 0.0f;
            #pragma unroll 8
            for (int c = lane; c < 1024; c += 32) {
                float e = __expf(row[c] - m);
                row[c] = e;
                ssum += e;
            }
            #pragma unroll
            for (int o = 16; o > 0; o >>= 1) ssum += __shfl_xor_sync(0xffffffffu, ssum, o);
            float inv = 1.0f / ssum;
            float* wrow = wrow_base + (size_t)(r0 + i) * 1024;
            #pragma unroll 8
            for (int c = lane; c < 1024; c += 32) {
                float w = row[c] * inv;
                row[c] = w;
                wrow[c] = w;
            }
        }
    }

    // ---- AV: attn[i,d] = sum_c P[i,c] * V[c,d] ----
    const int ai  = tid >> 3;             // 0..31
    const int ad0 = (tid & 7) * 8;        // 0..56
    float acc[8];
    #pragma unroll
    for (int j = 0; j < 8; j++) acc[j] = 0.0f;

    for (int ct = 0; ct < 8; ct++) {
        __syncthreads();                  // softmax done / prev compute done
        #pragma unroll
        for (int s = 0; s < 8; s++) {
            int idx = tid + 256 * s;
            int c  = idx >> 4;            // 0..127
            int d0 = (idx & 15) * 4;
            float4 v = *reinterpret_cast<const float4*>(vb + (size_t)(ct * CT + c) * 4096 + d0);
            *reinterpret_cast<float4*>(&KV[c * VS_STRIDE + d0]) = v;
        }
        __syncthreads();

        #pragma unroll 2
        for (int c4 = 0; c4 < CT; c4 += 4) {
            float4 p = *reinterpret_cast<const float4*>(&S[ai * 1024 + ct * CT + c4]);
            float pv[4] = {p.x, p.y, p.z, p.w};
            #pragma unroll
            for (int cc = 0; cc < 4; cc++) {
                float4 v0 = *reinterpret_cast<const float4*>(&KV[(c4 + cc) * VS_STRIDE + ad0]);
                float4 v1 = *reinterpret_cast<const float4*>(&KV[(c4 + cc) * VS_STRIDE + ad0 + 4]);
                acc[0] += pv[cc] * v0.x; acc[1] += pv[cc] * v0.y;
                acc[2] += pv[cc] * v0.z; acc[3] += pv[cc] * v0.w;
                acc[4] += pv[cc] * v1.x; acc[5] += pv[cc] * v1.y;
                acc[6] += pv[cc] * v1.z; acc[7] += pv[cc] * v1.w;
            }
        }
    }

    // out[bh>>4, r0+ai, (bh&15)*64 + ad0 + j]
    size_t obase = (size_t)(bh >> 4) * Nn * Ee + (size_t)(r0 + ai) * Ee + (bh & 15) * 64 + ad0;
    float4 o0 = {acc[0], acc[1], acc[2], acc[3]};
    float4 o1 = {acc[4], acc[5], acc[6], acc[7]};
    *reinterpret_cast<float4*>(&out_attn[obase])     = o0;
    *reinterpret_cast<float4*>(&out_attn[obase + 4]) = o1;
}

// ---------------------------------------------------------------------------
extern "C" void kernel_launch(void* const* d_in, const int* in_sizes, int n_in,
                              void* d_out, int out_size) {
    const float* query = (const float*)d_in[0];
    const float* key_  = (const float*)d_in[1];
    const float* value = (const float*)d_in[2];
    const float* ab    = (const float*)d_in[3];
    const float* Wq    = (const float*)d_in[4];
    const float* bq    = (const float*)d_in[5];
    const float* Wk    = (const float*)d_in[6];
    const float* bk    = (const float*)d_in[7];
    const float* Wv    = (const float*)d_in[8];
    const float* bv    = (const float*)d_in[9];

    float* out = (float*)d_out;
    const long long attn_elems = (long long)Bc * Nn * Ee;           // 4,194,304
    const long long w_elems    = (long long)BHn * Nn * Nn;          // 67,108,864
    float* attn_out = out;
    float* w_out = nullptr;
    if ((long long)out_size >= attn_elems + w_elems) w_out = out + attn_elems;

    // Projections
    {
        dim3 grid(Ee / 128, Mtot / 128, 3);
        proj_kernel<<<grid, 256>>>(query, key_, value, Wq, Wk, Wv, bq, bk, bv);
    }

    // Attention
    {
        static const int smem_bytes = SMEM_FLOATS * (int)sizeof(float); // 175104
        cudaFuncSetAttribute(attn_kernel, cudaFuncAttributeMaxDynamicSharedMemorySize, smem_bytes);
        dim3 grid(Nn / RT, BHn);
        attn_kernel<<<grid, 256, smem_bytes>>>(ab, attn_out, w_out);
    }
}

// round 3
// speedup vs baseline: 3.3745x; 3.3745x over previous
#include <cuda_runtime.h>
#include <cstdint>

#define Bc   4
#define Nn   1024
#define Ee   1024
#define BHn  64
#define Mtot 4096   // B*N

// Scratch for projected q/k/v in natural [B,N,E] layout.
__device__ float g_q[Mtot * Ee];
__device__ float g_k[Mtot * Ee];
__device__ float g_v[Mtot * Ee];
// Fallback weights buffer if the harness output only holds attn.
__device__ float g_w[(size_t)BHn * Nn * Nn];

// ===========================================================================
// bf16-split helpers + mma.sync (family-compatible, no tcgen05)
// ===========================================================================
static __device__ __forceinline__ uint32_t pack_bf16(float x0, float x1) {
    // result: lo half = bf16(x0), hi half = bf16(x1)
    uint32_t r;
    asm("cvt.rn.bf16x2.f32 %0, %1, %2;" : "=r"(r) : "f"(x1), "f"(x0));
    return r;
}
static __device__ __forceinline__ void split2(float x0, float x1, uint32_t& h, uint32_t& l) {
    h = pack_bf16(x0, x1);
    float h0 = __uint_as_float(h << 16);
    float h1 = __uint_as_float(h & 0xFFFF0000u);
    l = pack_bf16(x0 - h0, x1 - h1);
}
static __device__ __forceinline__ void mma_bf16(float* c, const uint32_t* a, const uint32_t* b) {
    asm volatile(
        "mma.sync.aligned.m16n8k16.row.col.f32.bf16.bf16.f32 "
        "{%0,%1,%2,%3}, {%4,%5,%6,%7}, {%8,%9}, {%0,%1,%2,%3};"
        : "+f"(c[0]), "+f"(c[1]), "+f"(c[2]), "+f"(c[3])
        : "r"(a[0]), "r"(a[1]), "r"(a[2]), "r"(a[3]), "r"(b[0]), "r"(b[1]));
}

// ===========================================================================
// Projection GEMM: C = X @ W^T + b via mma.sync bf16 3-product split.
// X[4096,1024], W[1024,1024] K-major. Tile 128x128, K-chunk 32, 256 thr.
// ===========================================================================
#define PSP 36  // kpair stride (uint32) per row
#define PROJ_SMEM_BYTES ((4 * 128 * PSP) * 4 + 512)

__global__ __launch_bounds__(256, 1) void proj_mma_kernel(
    const float* __restrict__ Xq, const float* __restrict__ Xk, const float* __restrict__ Xv,
    const float* __restrict__ Wq, const float* __restrict__ Wk, const float* __restrict__ Wv,
    const float* __restrict__ bq, const float* __restrict__ bk, const float* __restrict__ bv)
{
    extern __shared__ uint32_t psm[];
    uint32_t* XH = psm;
    uint32_t* XL = psm + 128 * PSP;
    uint32_t* WH = psm + 2 * 128 * PSP;
    uint32_t* WL = psm + 3 * 128 * PSP;
    float* bsm = (float*)(psm + 4 * 128 * PSP);

    const float* X; const float* W; const float* bias; float* C;
    if (blockIdx.z == 0)      { X = Xq; W = Wq; bias = bq; C = g_q; }
    else if (blockIdx.z == 1) { X = Xk; W = Wk; bias = bk; C = g_k; }
    else                      { X = Xv; W = Wv; bias = bv; C = g_v; }

    const int tid = threadIdx.x;
    const int w = tid >> 5, lane = tid & 31;
    const int g = lane >> 2, t = lane & 3;
    const int bm = blockIdx.x * 128, bn = blockIdx.y * 128;
    const int wm = w >> 2, wn = w & 3;

    if (tid < 128) bsm[tid] = bias[bn + tid];

    const float* Xb = X + (size_t)bm * 1024;
    const float* Wb = W + (size_t)bn * 1024;

    float4 xr[4], wr[4];
    #pragma unroll
    for (int s = 0; s < 4; s++) {
        int idx = tid + 256 * s, row = idx >> 3, q = idx & 7;
        xr[s] = *(const float4*)(Xb + (size_t)row * 1024 + q * 4);
        wr[s] = *(const float4*)(Wb + (size_t)row * 1024 + q * 4);
    }

    float acc[4][4][4];
    #pragma unroll
    for (int i = 0; i < 4; i++)
        #pragma unroll
        for (int j = 0; j < 4; j++)
            #pragma unroll
            for (int k = 0; k < 4; k++) acc[i][j][k] = 0.0f;

    for (int kc = 0; kc < 32; kc++) {
        __syncthreads();
        #pragma unroll
        for (int s = 0; s < 4; s++) {
            int idx = tid + 256 * s, row = idx >> 3, q = idx & 7;
            uint32_t h0, l0, h1, l1;
            split2(xr[s].x, xr[s].y, h0, l0); split2(xr[s].z, xr[s].w, h1, l1);
            *(uint2*)&XH[row * PSP + q * 2] = make_uint2(h0, h1);
            *(uint2*)&XL[row * PSP + q * 2] = make_uint2(l0, l1);
            split2(wr[s].x, wr[s].y, h0, l0); split2(wr[s].z, wr[s].w, h1, l1);
            *(uint2*)&WH[row * PSP + q * 2] = make_uint2(h0, h1);
            *(uint2*)&WL[row * PSP + q * 2] = make_uint2(l0, l1);
        }
        __syncthreads();
        if (kc < 31) {
            #pragma unroll
            for (int s = 0; s < 4; s++) {
                int idx = tid + 256 * s, row = idx >> 3, q = idx & 7;
                xr[s] = *(const float4*)(Xb + (size_t)row * 1024 + (kc + 1) * 32 + q * 4);
                wr[s] = *(const float4*)(Wb + (size_t)row * 1024 + (kc + 1) * 32 + q * 4);
            }
        }
        #pragma unroll
        for (int ks = 0; ks < 2; ks++) {
            uint32_t bhf[4][2], blf[4][2];
            #pragma unroll
            for (int nt = 0; nt < 4; nt++) {
                int rb = (wn * 32 + nt * 8 + g) * PSP + ks * 8 + t;
                bhf[nt][0] = WH[rb]; bhf[nt][1] = WH[rb + 4];
                blf[nt][0] = WL[rb]; blf[nt][1] = WL[rb + 4];
            }
            #pragma unroll
            for (int mt = 0; mt < 4; mt++) {
                int ra = (wm * 64 + mt * 16 + g) * PSP + ks * 8 + t;
                uint32_t ah[4] = {XH[ra], XH[ra + 8 * PSP], XH[ra + 4], XH[ra + 8 * PSP + 4]};
                uint32_t al[4] = {XL[ra], XL[ra + 8 * PSP], XL[ra + 4], XL[ra + 8 * PSP + 4]};
                #pragma unroll
                for (int nt = 0; nt < 4; nt++) {
                    mma_bf16(acc[mt][nt], ah, bhf[nt]);
                    mma_bf16(acc[mt][nt], ah, blf[nt]);
                    mma_bf16(acc[mt][nt], al, bhf[nt]);
                }
            }
        }
    }

    #pragma unroll
    for (int mt = 0; mt < 4; mt++) {
        int row = wm * 64 + mt * 16 + g;
        #pragma unroll
        for (int nt = 0; nt < 4; nt++) {
            int col = wn * 32 + nt * 8 + 2 * t;
            float bx = bsm[col], by = bsm[col + 1];
            float* p0 = C + (size_t)(bm + row) * 1024 + bn + col;
            *(float2*)p0 = make_float2(acc[mt][nt][0] + bx, acc[mt][nt][1] + by);
            float* p1 = p0 + (size_t)8 * 1024;
            *(float2*)p1 = make_float2(acc[mt][nt][2] + bx, acc[mt][nt][3] + by);
        }
    }
}

// ===========================================================================
// Attention: one CTA per (bh, 32-row tile); mma.sync for scores and AV.
// ===========================================================================
#define SSTR 1036
#define QH_OFF (32 * SSTR)          // words
#define QL_OFF (QH_OFF + 32 * 36)
#define KH_OFF (QL_OFF + 32 * 36)
#define KL_OFF (KH_OFF + 4608)
#define ATTN_SMEM_WORDS (KL_OFF + 4608)
#define ATTN_SMEM_BYTES (ATTN_SMEM_WORDS * 4)   // 178688

__global__ __launch_bounds__(256, 1) void attn_mma_kernel(
    const float* __restrict__ bias, float* __restrict__ out_attn, float* __restrict__ w_out)
{
    extern __shared__ float sm[];
    float* S = sm;
    uint32_t* QH = (uint32_t*)(sm + QH_OFF);
    uint32_t* QL = (uint32_t*)(sm + QL_OFF);
    uint32_t* KH = (uint32_t*)(sm + KH_OFF);   // also VH ([64][68])
    uint32_t* KL = (uint32_t*)(sm + KL_OFF);   // also VL

    const int tid = threadIdx.x;
    const int w = tid >> 5, lane = tid & 31;
    const int g = lane >> 2, t = lane & 3;
    const int bh = blockIdx.y;
    const int r0 = blockIdx.x * 32;

    const float* qb = g_q + bh * 64;
    const float* kb = g_k + bh * 64;
    const float* vb = g_v + bh * 64;
    const float* bsrc = bias + (size_t)(bh & 3) * Nn * Nn;
    float* wbase = (w_out != nullptr) ? w_out : g_w;
    float* wrow_base = wbase + (size_t)bh * Nn * Nn;

    // ---- Q load + bf16 split ----
    #pragma unroll
    for (int s = 0; s < 2; s++) {
        int idx = tid + 256 * s, row = idx >> 4, q = idx & 15;
        float4 v = *(const float4*)(qb + (size_t)(r0 + row) * 4096 + q * 4);
        uint32_t h0, l0, h1, l1;
        split2(v.x, v.y, h0, l0); split2(v.z, v.w, h1, l1);
        *(uint2*)&QH[row * 36 + q * 2] = make_uint2(h0, h1);
        *(uint2*)&QL[row * 36 + q * 2] = make_uint2(l0, l1);
    }

    // ---- prefetch K tile 0 ----
    float4 kr[8];
    #pragma unroll
    for (int s = 0; s < 8; s++) {
        int idx = tid + 256 * s, row = idx >> 4, q = idx & 15;
        kr[s] = *(const float4*)(kb + (size_t)row * 4096 + q * 4);
    }

    const int wm = w >> 2, wn = w & 3;
    const int m0 = wm * 16, n0s = wn * 32;

    // ---- scores: S[i][c] = Q.K^T + bias ----
    for (int ct = 0; ct < 8; ct++) {
        __syncthreads();
        #pragma unroll
        for (int s = 0; s < 8; s++) {
            int idx = tid + 256 * s, row = idx >> 4, q = idx & 15;
            uint32_t h0, l0, h1, l1;
            split2(kr[s].x, kr[s].y, h0, l0); split2(kr[s].z, kr[s].w, h1, l1);
            *(uint2*)&KH[row * 36 + q * 2] = make_uint2(h0, h1);
            *(uint2*)&KL[row * 36 + q * 2] = make_uint2(l0, l1);
        }
        __syncthreads();
        if (ct < 7) {
            #pragma unroll
            for (int s = 0; s < 8; s++) {
                int idx = tid + 256 * s, row = idx >> 4, q = idx & 15;
                kr[s] = *(const float4*)(kb + (size_t)((ct + 1) * 128 + row) * 4096 + q * 4);
            }
        }
        float sacc[4][4];
        #pragma unroll
        for (int i = 0; i < 4; i++)
            #pragma unroll
            for (int j = 0; j < 4; j++) sacc[i][j] = 0.0f;

        #pragma unroll
        for (int ks = 0; ks < 4; ks++) {
            uint32_t bhf[4][2], blf[4][2];
            #pragma unroll
            for (int nt = 0; nt < 4; nt++) {
                int rb = (n0s + nt * 8 + g) * 36 + ks * 8 + t;
                bhf[nt][0] = KH[rb]; bhf[nt][1] = KH[rb + 4];
                blf[nt][0] = KL[rb]; blf[nt][1] = KL[rb + 4];
            }
            int ra = (m0 + g) * 36 + ks * 8 + t;
            uint32_t ah[4] = {QH[ra], QH[ra + 8 * 36], QH[ra + 4], QH[ra + 8 * 36 + 4]};
            uint32_t al[4] = {QL[ra], QL[ra + 8 * 36], QL[ra + 4], QL[ra + 8 * 36 + 4]};
            #pragma unroll
            for (int nt = 0; nt < 4; nt++) {
                mma_bf16(sacc[nt], ah, bhf[nt]);
                mma_bf16(sacc[nt], ah, blf[nt]);
                mma_bf16(sacc[nt], al, bhf[nt]);
            }
        }

        int rowl = m0 + g;
        #pragma unroll
        for (int nt = 0; nt < 4; nt++) {
            int coll = ct * 128 + n0s + nt * 8 + 2 * t;
            float2 b0 = *(const float2*)(bsrc + (size_t)(r0 + rowl) * 1024 + coll);
            float2 b1 = *(const float2*)(bsrc + (size_t)(r0 + rowl + 8) * 1024 + coll);
            *(float2*)&S[rowl * SSTR + coll] =
                make_float2(sacc[nt][0] + b0.x, sacc[nt][1] + b0.y);
            *(float2*)&S[(rowl + 8) * SSTR + coll] =
                make_float2(sacc[nt][2] + b1.x, sacc[nt][3] + b1.y);
        }
    }
    __syncthreads();

    // ---- prefetch V tile 0 (overlaps softmax) ----
    float4 vr[8];
    #pragma unroll
    for (int s = 0; s < 4; s++) {
        int idx = tid + 256 * s, cp = idx & 63, dq = idx >> 6;
        vr[2 * s]     = *(const float4*)(vb + (size_t)(2 * cp) * 4096 + dq * 4);
        vr[2 * s + 1] = *(const float4*)(vb + (size_t)(2 * cp + 1) * 4096 + dq * 4);
    }

    // ---- softmax per row + stream weights ----
    {
        #pragma unroll
        for (int rr = 0; rr < 4; rr++) {
            int i = w * 4 + rr;
            float* row = &S[i * SSTR];
            float m = -3.0e38f;
            #pragma unroll 8
            for (int c = lane; c < 1024; c += 32) m = fmaxf(m, row[c]);
            #pragma unroll
            for (int o = 16; o > 0; o >>= 1) m = fmaxf(m, __shfl_xor_sync(0xffffffffu, m, o));
            float ssum = 0.0f;
            #pragma unroll 8
            for (int c = lane; c < 1024; c += 32) {
                float e = __expf(row[c] - m);
                row[c] = e;
                ssum += e;
            }
            #pragma unroll
            for (int o = 16; o > 0; o >>= 1) ssum += __shfl_xor_sync(0xffffffffu, ssum, o);
            float inv = 1.0f / ssum;
            float* wrow = wrow_base + (size_t)(r0 + i) * 1024;
            #pragma unroll 8
            for (int c = lane; c < 1024; c += 32) {
                float ww = row[c] * inv;
                row[c] = ww;
                wrow[c] = ww;
            }
        }
    }

    // ---- AV: O = P @ V (k split across warp pairs) ----
    const int rm = w & 1, rn = (w >> 1) & 1, kh = w >> 2;
    float oacc[4][4];
    #pragma unroll
    for (int i = 0; i < 4; i++)
        #pragma unroll
        for (int j = 0; j < 4; j++) oacc[i][j] = 0.0f;

    uint32_t* VH = KH;
    uint32_t* VL = KL;

    for (int ct = 0; ct < 8; ct++) {
        __syncthreads();
        #pragma unroll
        for (int s = 0; s < 4; s++) {
            int idx = tid + 256 * s, cp = idx & 63, dq = idx >> 6;
            float4 a = vr[2 * s], b = vr[2 * s + 1];
            float av[4] = {a.x, a.y, a.z, a.w}, bv2[4] = {b.x, b.y, b.z, b.w};
            #pragma unroll
            for (int j = 0; j < 4; j++) {
                uint32_t h, l;
                split2(av[j], bv2[j], h, l);
                VH[(dq * 4 + j) * 68 + cp] = h;
                VL[(dq * 4 + j) * 68 + cp] = l;
            }
        }
        __syncthreads();
        if (ct < 7) {
            #pragma unroll
            for (int s = 0; s < 4; s++) {
                int idx = tid + 256 * s, cp = idx & 63, dq = idx >> 6;
                vr[2 * s]     = *(const float4*)(vb + (size_t)((ct + 1) * 128 + 2 * cp) * 4096 + dq * 4);
                vr[2 * s + 1] = *(const float4*)(vb + (size_t)((ct + 1) * 128 + 2 * cp + 1) * 4096 + dq * 4);
            }
        }
        #pragma unroll
        for (int kk = 0; kk < 4; kk++) {
            int ks = kh * 4 + kk;
            int arow = rm * 16 + g;
            int acol = ct * 128 + ks * 16 + 2 * t;
            float2 x0 = *(const float2*)&S[arow * SSTR + acol];
            float2 x1 = *(const float2*)&S[(arow + 8) * SSTR + acol];
            float2 x2 = *(const float2*)&S[arow * SSTR + acol + 8];
            float2 x3 = *(const float2*)&S[(arow + 8) * SSTR + acol + 8];
            uint32_t ah[4], al[4];
            split2(x0.x, x0.y, ah[0], al[0]);
            split2(x1.x, x1.y, ah[1], al[1]);
            split2(x2.x, x2.y, ah[2], al[2]);
            split2(x3.x, x3.y, ah[3], al[3]);
            #pragma unroll
            for (int nt = 0; nt < 4; nt++) {
                int rb = (rn * 32 + nt * 8 + g) * 68 + ks * 8 + t;
                uint32_t bh2[2] = {VH[rb], VH[rb + 4]};
                uint32_t bl2[2] = {VL[rb], VL[rb + 4]};
                mma_bf16(oacc[nt], ah, bh2);
                mma_bf16(oacc[nt], ah, bl2);
                mma_bf16(oacc[nt], al, bh2);
            }
        }
    }

    // ---- combine k-halves and store with output scramble ----
    float* Opart = sm + QH_OFF;  // reuse Q area, stride 68
    if (w >= 4) {
        #pragma unroll
        for (int nt = 0; nt < 4; nt++) {
            int row = rm * 16 + g, col = rn * 32 + nt * 8 + 2 * t;
            *(float2*)&Opart[row * 68 + col] = make_float2(oacc[nt][0], oacc[nt][1]);
            *(float2*)&Opart[(row + 8) * 68 + col] = make_float2(oacc[nt][2], oacc[nt][3]);
        }
    }
    __syncthreads();
    if (w < 4) {
        size_t ob = (size_t)(bh >> 4) * Nn * Ee + (size_t)(bh & 15) * 64;
        #pragma unroll
        for (int nt = 0; nt < 4; nt++) {
            int row = rm * 16 + g, col = rn * 32 + nt * 8 + 2 * t;
            float2 p0 = *(float2*)&Opart[row * 68 + col];
            float2 p1 = *(float2*)&Opart[(row + 8) * 68 + col];
            *(float2*)&out_attn[ob + (size_t)(r0 + row) * Ee + col] =
                make_float2(oacc[nt][0] + p0.x, oacc[nt][1] + p0.y);
            *(float2*)&out_attn[ob + (size_t)(r0 + row + 8) * Ee + col] =
                make_float2(oacc[nt][2] + p1.x, oacc[nt][3] + p1.y);
        }
    }
}

// ---------------------------------------------------------------------------
extern "C" void kernel_launch(void* const* d_in, const int* in_sizes, int n_in,
                              void* d_out, int out_size) {
    const float* query = (const float*)d_in[0];
    const float* key_  = (const float*)d_in[1];
    const float* value = (const float*)d_in[2];
    const float* ab    = (const float*)d_in[3];
    const float* Wq    = (const float*)d_in[4];
    const float* bq    = (const float*)d_in[5];
    const float* Wk    = (const float*)d_in[6];
    const float* bk    = (const float*)d_in[7];
    const float* Wv    = (const float*)d_in[8];
    const float* bv    = (const float*)d_in[9];

    float* out = (float*)d_out;
    const long long attn_elems = (long long)Bc * Nn * Ee;
    const long long w_elems    = (long long)BHn * Nn * Nn;
    float* attn_out = out;
    float* w_out = nullptr;
    if ((long long)out_size >= attn_elems + w_elems) w_out = out + attn_elems;

    {
        cudaFuncSetAttribute(proj_mma_kernel, cudaFuncAttributeMaxDynamicSharedMemorySize,
                             PROJ_SMEM_BYTES);
        dim3 grid(Mtot / 128, Ee / 128, 3);
        proj_mma_kernel<<<grid, 256, PROJ_SMEM_BYTES>>>(query, key_, value, Wq, Wk, Wv, bq, bk, bv);
    }
    {
        cudaFuncSetAttribute(attn_mma_kernel, cudaFuncAttributeMaxDynamicSharedMemorySize,
                             ATTN_SMEM_BYTES);
        dim3 grid(Nn / 32, BHn);
        attn_mma_kernel<<<grid, 256, ATTN_SMEM_BYTES>>>(ab, attn_out, w_out);
    }
}